// round 14
// baseline (speedup 1.0000x reference)
#include <cuda_runtime.h>

// ---------------- problem constants ----------------
#define T      256
#define Hd     1024
#define E      256
#define Id     256
#define TOPK   8
#define NGROUP 8
#define GSIZE  32          // E / NGROUP
#define TOPKG  4
#define SCALE  2.5f

#define TC     16          // tokens per chunk per expert CTA
#define NP     8           // token pairs (TC/2)
#define XPF    18          // floats per smem row (16 tokens + 2 pad, kills STS conflicts)
#define XPU    9           // u64 per smem row

typedef unsigned long long u64;

// ---------------- device scratch (no allocations allowed) ----------------
__device__ float g_logits[T * E];
__device__ int   g_cnt[E];
__device__ int   g_tok[E * T];
__device__ float g_wt[E * T];

// ---------------- packed f32x2 helpers ----------------
__device__ __forceinline__ u64 ffma2(u64 a, u64 b, u64 c) {
    u64 d;
    asm("fma.rn.f32x2 %0, %1, %2, %3;" : "=l"(d) : "l"(a), "l"(b), "l"(c));
    return d;
}
__device__ __forceinline__ u64 dup2(float v) {
    u64 d;
    asm("mov.b64 %0, {%1, %1};" : "=l"(d) : "f"(v));
    return d;
}
__device__ __forceinline__ float2 unpack2(u64 v) {
    float2 f;
    asm("mov.b64 {%0, %1}, %2;" : "=f"(f.x), "=f"(f.y) : "l"(v));
    return f;
}

// ---------------- kernel 0: zero output + expert counters ----------------
__global__ void zero_kernel(float* __restrict__ y) {
    int i = blockIdx.x * 256 + threadIdx.x;
    if (i < T * Hd) y[i] = 0.0f;
    if (i < E) g_cnt[i] = 0;
}

// ---------------- kernel 1: gate logits  C[t][e] = sum_h X[t][h] * W[e][h] ----------------
__global__ __launch_bounds__(256) void gate_gemm(const float* __restrict__ X,
                                                 const float* __restrict__ W) {
    __shared__ float Xs[32][65];   // [k][t], padded
    __shared__ float Ws[32][65];   // [k][e], padded
    int t0 = blockIdx.x * 64;
    int e0 = blockIdx.y * 64;
    int tid = threadIdx.x;
    int tx = tid & 15;        // expert micro-tile
    int ty = tid >> 4;        // token micro-tile
    float acc[4][4];
#pragma unroll
    for (int i = 0; i < 4; i++)
#pragma unroll
        for (int j = 0; j < 4; j++) acc[i][j] = 0.0f;

    for (int k0 = 0; k0 < Hd; k0 += 32) {
#pragma unroll
        for (int l = 0; l < 8; l++) {
            int idx = tid + l * 256;
            int r = idx >> 5;      // 0..63
            int kk = idx & 31;
            Xs[kk][r] = X[(size_t)(t0 + r) * Hd + k0 + kk];
            Ws[kk][r] = W[(size_t)(e0 + r) * Hd + k0 + kk];
        }
        __syncthreads();
#pragma unroll
        for (int kk = 0; kk < 32; kk++) {
            float a[4], b[4];
#pragma unroll
            for (int i = 0; i < 4; i++) a[i] = Xs[kk][ty * 4 + i];
#pragma unroll
            for (int j = 0; j < 4; j++) b[j] = Ws[kk][tx * 4 + j];
#pragma unroll
            for (int i = 0; i < 4; i++)
#pragma unroll
                for (int j = 0; j < 4; j++) acc[i][j] = fmaf(a[i], b[j], acc[i][j]);
        }
        __syncthreads();
    }
#pragma unroll
    for (int i = 0; i < 4; i++)
#pragma unroll
        for (int j = 0; j < 4; j++)
            g_logits[(t0 + ty * 4 + i) * E + e0 + tx * 4 + j] = acc[i][j];
}

// ---------------- kernel 2: per-token routing (noaux_tc) ----------------
__global__ void route_kernel(const float* __restrict__ e_bias) {
    int t = blockIdx.x * blockDim.x + threadIdx.x;
    if (t >= T) return;
    const float* lrow = g_logits + t * E;

    float sc[E];
#pragma unroll 4
    for (int e = 0; e < E; e++) {
        float s = 1.0f / (1.0f + expf(-lrow[e]));
        sc[e] = s + e_bias[e];
    }

    // group score = sum of top-2 corrected scores within each group of 32
    float gs[NGROUP];
    for (int g = 0; g < NGROUP; g++) {
        float m1 = -1e30f, m2 = -1e30f;
        for (int j = 0; j < GSIZE; j++) {
            float v = sc[g * GSIZE + j];
            if (v > m1) { m2 = m1; m1 = v; }
            else if (v > m2) { m2 = v; }
        }
        gs[g] = m1 + m2;
    }

    // top-4 groups (strict > keeps lowest index on ties, matching lax.top_k)
    unsigned gmask = 0;
    for (int r = 0; r < TOPKG; r++) {
        float best = -1e30f; int bi = 0;
        for (int g = 0; g < NGROUP; g++)
            if (!((gmask >> g) & 1u) && gs[g] > best) { best = gs[g]; bi = g; }
        gmask |= 1u << bi;
    }

    // top-8 experts among the 128 unmasked candidates (stable insertion)
    float bv[TOPK]; int bix[TOPK];
#pragma unroll
    for (int r = 0; r < TOPK; r++) { bv[r] = -1e30f; bix[r] = 0; }
    for (int e = 0; e < E; e++) {
        if (!((gmask >> (e >> 5)) & 1u)) continue;
        float v = sc[e];
        if (v <= bv[TOPK - 1]) continue;
        int pos = TOPK - 1;
        while (pos > 0 && bv[pos - 1] < v) {
            bv[pos] = bv[pos - 1]; bix[pos] = bix[pos - 1]; pos--;
        }
        bv[pos] = v; bix[pos] = e;
    }

    // weights come from RAW sigmoid scores of the selected experts
    float wv[TOPK]; float wsum = 0.0f;
#pragma unroll
    for (int r = 0; r < TOPK; r++) {
        wv[r] = 1.0f / (1.0f + expf(-lrow[bix[r]]));
        wsum += wv[r];
    }
    float inv = SCALE / (wsum + 1e-20f);
#pragma unroll
    for (int r = 0; r < TOPK; r++) {
        int e = bix[r];
        int pos = atomicAdd(&g_cnt[e], 1);
        g_tok[e * T + pos] = t;
        g_wt[e * T + pos]  = wv[r] * inv;
    }
}

// ---------------- kernel 3: expert MLPs (routed + shared) ----------------
// blockIdx.x < E      : routed expert blockIdx.x, tokens from g_tok/g_wt
// blockIdx.x >= E     : shared expert over token slice, weight 1.0
// Layout in smem (dynamic):
//   xs : [Hd][XPF] floats  — xs[h*XPF + t] = x[token_t][h] (pairs -> u64 lanes)
//   as : [Id][XPF] floats  — as[i*XPF + t] = w_t * silu(h1) * h3
__global__ __launch_bounds__(256) void expert_kernel(
    const float* __restrict__ x,
    const float* __restrict__ w_gate, const float* __restrict__ w_up,
    const float* __restrict__ w_down,
    const float* __restrict__ sw_gate, const float* __restrict__ sw_up,
    const float* __restrict__ sw_down,
    float* __restrict__ y)
{
    extern __shared__ float smem[];
    float* xs = smem;                      // Hd * XPF floats
    float* as = smem + Hd * XPF;           // Id * XPF floats
    const u64* xsu = (const u64*)xs;
    const u64* asu = (const u64*)as;
    __shared__ int   s_tok[TC];
    __shared__ float s_w[TC];

    const int tid = threadIdx.x;
    const int e = blockIdx.x;
    const bool sh = (e >= E);

    const float *Wg, *Wu, *Wd;
    int nt, base = 0;
    if (sh) {
        Wg = sw_gate; Wu = sw_up; Wd = sw_down;
        nt = TC; base = (e - E) * TC;
    } else {
        size_t off = (size_t)e * Hd * Id;
        Wg = w_gate + off; Wu = w_up + off; Wd = w_down + off;
        nt = g_cnt[e];
    }
    const int nchunk = (nt + TC - 1) / TC;

    for (int ch = 0; ch < nchunk; ch++) {
        if (tid < TC) {
            int slot = ch * TC + tid;
            if (sh)             { s_tok[tid] = base + tid;          s_w[tid] = 1.0f; }
            else if (slot < nt) { s_tok[tid] = g_tok[e * T + slot]; s_w[tid] = g_wt[e * T + slot]; }
            else                { s_tok[tid] = 0;                   s_w[tid] = 0.0f; }
        }
        __syncthreads();

        // gather X rows (coalesced LDG; 2-way-conflict STS via XPF=18 pitch)
        for (int idx = tid; idx < TC * Hd; idx += 256) {
            int t = idx >> 10;          // / Hd
            int h = idx & (Hd - 1);
            xs[h * XPF + t] = x[(size_t)s_tok[t] * Hd + h];
        }
        __syncthreads();

        // ---- gate + up projections: thread owns column i of I ----
        {
            const int i = tid;
            u64 a1[NP], a3[NP];
#pragma unroll
            for (int p = 0; p < NP; p++) { a1[p] = 0ull; a3[p] = 0ull; }
            const float* wg = Wg + i;
            const float* wu = Wu + i;
#pragma unroll 4
            for (int h = 0; h < Hd; h++) {
                u64 g2 = dup2(wg[h * Id]);
                u64 u2 = dup2(wu[h * Id]);
                const u64* xr = xsu + h * XPU;
#pragma unroll
                for (int p = 0; p < NP; p++) {
                    u64 xv = xr[p];
                    a1[p] = ffma2(xv, g2, a1[p]);
                    a3[p] = ffma2(xv, u2, a3[p]);
                }
            }
            // activation: A = w_t * silu(h1) * h3   (padded slots have w=0)
#pragma unroll
            for (int p = 0; p < NP; p++) {
                float2 h1 = unpack2(a1[p]);
                float2 h3 = unpack2(a3[p]);
                float ax = s_w[2 * p]     * (h1.x / (1.0f + expf(-h1.x))) * h3.x;
                float ay = s_w[2 * p + 1] * (h1.y / (1.0f + expf(-h1.y))) * h3.y;
                as[i * XPF + 2 * p]     = ax;
                as[i * XPF + 2 * p + 1] = ay;
            }
        }
        __syncthreads();

        // ---- down projection: 4 column chunks of 256, thread owns one column ----
        for (int c = 0; c < Hd / Id; c++) {
            const int col = c * Id + tid;
            u64 acc[NP];
#pragma unroll
            for (int p = 0; p < NP; p++) acc[p] = 0ull;
            const float* wd = Wd + col;
#pragma unroll 4
            for (int i2 = 0; i2 < Id; i2++) {
                u64 d2 = dup2(wd[i2 * Hd]);
                const u64* ar = asu + i2 * XPU;
#pragma unroll
                for (int p = 0; p < NP; p++) acc[p] = ffma2(ar[p], d2, acc[p]);
            }
#pragma unroll
            for (int p = 0; p < NP; p++) {
                float2 v = unpack2(acc[p]);
                if (s_w[2 * p] != 0.0f)
                    atomicAdd(&y[(size_t)s_tok[2 * p] * Hd + col], v.x);
                if (s_w[2 * p + 1] != 0.0f)
                    atomicAdd(&y[(size_t)s_tok[2 * p + 1] * Hd + col], v.y);
            }
        }
        __syncthreads();   // before next chunk overwrites xs/as
    }
}

// ---------------- launch ----------------
extern "C" void kernel_launch(void* const* d_in, const int* in_sizes, int n_in,
                              void* d_out, int out_size) {
    const float* x       = (const float*)d_in[0];   // [1,1,T,H]
    const float* gate_w  = (const float*)d_in[1];   // [E,H]
    const float* e_bias  = (const float*)d_in[2];   // [E]
    const float* w_gate  = (const float*)d_in[3];   // [E,H,I]
    const float* w_up    = (const float*)d_in[4];   // [E,H,I]
    const float* w_down  = (const float*)d_in[5];   // [E,I,H]
    const float* sw_gate = (const float*)d_in[6];   // [H,I]
    const float* sw_up   = (const float*)d_in[7];   // [H,I]
    const float* sw_down = (const float*)d_in[8];   // [I,H]
    float* y = (float*)d_out;                       // [T*H] fp32

    const int SMEM_EXPERT = (Hd * XPF + Id * XPF) * (int)sizeof(float);  // 92160 B
    cudaFuncSetAttribute(expert_kernel,
                         cudaFuncAttributeMaxDynamicSharedMemorySize, SMEM_EXPERT);

    zero_kernel<<<(T * Hd + 255) / 256, 256>>>(y);
    gate_gemm<<<dim3(T / 64, E / 64), 256>>>(x, gate_w);
    route_kernel<<<(T + 31) / 32, 32>>>(e_bias);
    expert_kernel<<<E + T / TC, 256, SMEM_EXPERT>>>(
        x, w_gate, w_up, w_down, sw_gate, sw_up, sw_down, y);
}

// round 15
// speedup vs baseline: 1.6613x; 1.6613x over previous
#include <cuda_runtime.h>

// ---------------- problem constants ----------------
#define T      256
#define Hd     1024
#define E      256
#define Id     256
#define TOPK   8
#define NGROUP 8
#define GSIZE  32          // E / NGROUP
#define TOPKG  4
#define SCALE  2.5f

#define TC     16          // tokens per chunk per expert CTA
#define NP     8           // token pairs (TC/2)
#define XPF    18          // floats per smem row (16 tokens + 2 pad)
#define XPU    9           // u64 per smem row
#define PF     8           // prefetch depth, gate/up weight loads (x2 arrays = 16 LDG in flight)
#define DPF    16          // prefetch depth, down weight loads

typedef unsigned long long u64;

// ---------------- device scratch (no allocations allowed) ----------------
__device__ float g_logits[T * E];
__device__ int   g_cnt[E];
__device__ int   g_tok[E * T];
__device__ float g_wt[E * T];

// ---------------- packed f32x2 helpers ----------------
__device__ __forceinline__ u64 ffma2(u64 a, u64 b, u64 c) {
    u64 d;
    asm("fma.rn.f32x2 %0, %1, %2, %3;" : "=l"(d) : "l"(a), "l"(b), "l"(c));
    return d;
}
__device__ __forceinline__ u64 dup2(float v) {
    u64 d;
    asm("mov.b64 %0, {%1, %1};" : "=l"(d) : "f"(v));
    return d;
}
__device__ __forceinline__ float2 unpack2(u64 v) {
    float2 f;
    asm("mov.b64 {%0, %1}, %2;" : "=f"(f.x), "=f"(f.y) : "l"(v));
    return f;
}

// ---------------- kernel 0: zero output + expert counters ----------------
__global__ void zero_kernel(float* __restrict__ y) {
    int i = blockIdx.x * 256 + threadIdx.x;
    if (i < T * Hd) y[i] = 0.0f;
    if (i < E) g_cnt[i] = 0;
}

// ---------------- kernel 1: gate logits ----------------
__global__ __launch_bounds__(256) void gate_gemm(const float* __restrict__ X,
                                                 const float* __restrict__ W) {
    __shared__ float Xs[32][65];
    __shared__ float Ws[32][65];
    int t0 = blockIdx.x * 64;
    int e0 = blockIdx.y * 64;
    int tid = threadIdx.x;
    int tx = tid & 15;
    int ty = tid >> 4;
    float acc[4][4];
#pragma unroll
    for (int i = 0; i < 4; i++)
#pragma unroll
        for (int j = 0; j < 4; j++) acc[i][j] = 0.0f;

    for (int k0 = 0; k0 < Hd; k0 += 32) {
#pragma unroll
        for (int l = 0; l < 8; l++) {
            int idx = tid + l * 256;
            int r = idx >> 5;
            int kk = idx & 31;
            Xs[kk][r] = X[(size_t)(t0 + r) * Hd + k0 + kk];
            Ws[kk][r] = W[(size_t)(e0 + r) * Hd + k0 + kk];
        }
        __syncthreads();
#pragma unroll
        for (int kk = 0; kk < 32; kk++) {
            float a[4], b[4];
#pragma unroll
            for (int i = 0; i < 4; i++) a[i] = Xs[kk][ty * 4 + i];
#pragma unroll
            for (int j = 0; j < 4; j++) b[j] = Ws[kk][tx * 4 + j];
#pragma unroll
            for (int i = 0; i < 4; i++)
#pragma unroll
                for (int j = 0; j < 4; j++) acc[i][j] = fmaf(a[i], b[j], acc[i][j]);
        }
        __syncthreads();
    }
#pragma unroll
    for (int i = 0; i < 4; i++)
#pragma unroll
        for (int j = 0; j < 4; j++)
            g_logits[(t0 + ty * 4 + i) * E + e0 + tx * 4 + j] = acc[i][j];
}

// ---------------- kernel 2: per-token routing (noaux_tc) ----------------
__global__ void route_kernel(const float* __restrict__ e_bias) {
    int t = blockIdx.x * blockDim.x + threadIdx.x;
    if (t >= T) return;
    const float* lrow = g_logits + t * E;

    float sc[E];
#pragma unroll 4
    for (int e = 0; e < E; e++) {
        float s = 1.0f / (1.0f + expf(-lrow[e]));
        sc[e] = s + e_bias[e];
    }

    float gs[NGROUP];
    for (int g = 0; g < NGROUP; g++) {
        float m1 = -1e30f, m2 = -1e30f;
        for (int j = 0; j < GSIZE; j++) {
            float v = sc[g * GSIZE + j];
            if (v > m1) { m2 = m1; m1 = v; }
            else if (v > m2) { m2 = v; }
        }
        gs[g] = m1 + m2;
    }

    unsigned gmask = 0;
    for (int r = 0; r < TOPKG; r++) {
        float best = -1e30f; int bi = 0;
        for (int g = 0; g < NGROUP; g++)
            if (!((gmask >> g) & 1u) && gs[g] > best) { best = gs[g]; bi = g; }
        gmask |= 1u << bi;
    }

    float bv[TOPK]; int bix[TOPK];
#pragma unroll
    for (int r = 0; r < TOPK; r++) { bv[r] = -1e30f; bix[r] = 0; }
    for (int e = 0; e < E; e++) {
        if (!((gmask >> (e >> 5)) & 1u)) continue;
        float v = sc[e];
        if (v <= bv[TOPK - 1]) continue;
        int pos = TOPK - 1;
        while (pos > 0 && bv[pos - 1] < v) {
            bv[pos] = bv[pos - 1]; bix[pos] = bix[pos - 1]; pos--;
        }
        bv[pos] = v; bix[pos] = e;
    }

    float wv[TOPK]; float wsum = 0.0f;
#pragma unroll
    for (int r = 0; r < TOPK; r++) {
        wv[r] = 1.0f / (1.0f + expf(-lrow[bix[r]]));
        wsum += wv[r];
    }
    float inv = SCALE / (wsum + 1e-20f);
#pragma unroll
    for (int r = 0; r < TOPK; r++) {
        int e = bix[r];
        int pos = atomicAdd(&g_cnt[e], 1);
        g_tok[e * T + pos] = t;
        g_wt[e * T + pos]  = wv[r] * inv;
    }
}

// ---------------- kernel 3: expert MLPs (routed + shared) ----------------
// Register double-buffered weight prefetch: keeps 16 LDGs in flight per warp
// (gate/up) so per-SM outstanding bytes (~32KB) exceed the BW*latency product
// needed to saturate DRAM.
__global__ __launch_bounds__(256, 2) void expert_kernel(
    const float* __restrict__ x,
    const float* __restrict__ w_gate, const float* __restrict__ w_up,
    const float* __restrict__ w_down,
    const float* __restrict__ sw_gate, const float* __restrict__ sw_up,
    const float* __restrict__ sw_down,
    float* __restrict__ y)
{
    extern __shared__ float smem[];
    float* xs = smem;                      // Hd * XPF floats
    float* as = smem + Hd * XPF;           // Id * XPF floats
    const u64* xsu = (const u64*)xs;
    const u64* asu = (const u64*)as;
    __shared__ int   s_tok[TC];
    __shared__ float s_w[TC];

    const int tid = threadIdx.x;
    const int e = blockIdx.x;
    const bool sh = (e >= E);

    const float *Wg, *Wu, *Wd;
    int nt, base = 0;
    if (sh) {
        Wg = sw_gate; Wu = sw_up; Wd = sw_down;
        nt = TC; base = (e - E) * TC;
    } else {
        size_t off = (size_t)e * Hd * Id;
        Wg = w_gate + off; Wu = w_up + off; Wd = w_down + off;
        nt = g_cnt[e];
    }
    const int nchunk = (nt + TC - 1) / TC;

    for (int ch = 0; ch < nchunk; ch++) {
        if (tid < TC) {
            int slot = ch * TC + tid;
            if (sh)             { s_tok[tid] = base + tid;          s_w[tid] = 1.0f; }
            else if (slot < nt) { s_tok[tid] = g_tok[e * T + slot]; s_w[tid] = g_wt[e * T + slot]; }
            else                { s_tok[tid] = 0;                   s_w[tid] = 0.0f; }
        }
        __syncthreads();

        // gather X rows (coalesced LDG)
        for (int idx = tid; idx < TC * Hd; idx += 256) {
            int t = idx >> 10;          // / Hd
            int h = idx & (Hd - 1);
            xs[h * XPF + t] = x[(size_t)s_tok[t] * Hd + h];
        }
        __syncthreads();

        // ---- gate + up projections: thread owns column i of I ----
        {
            const int i = tid;
            u64 a1[NP], a3[NP];
#pragma unroll
            for (int p = 0; p < NP; p++) { a1[p] = 0ull; a3[p] = 0ull; }
            const float* wg = Wg + i;
            const float* wu = Wu + i;

            float bg[PF], bu[PF];
#pragma unroll
            for (int j = 0; j < PF; j++) {
                bg[j] = wg[j * Id];
                bu[j] = wu[j * Id];
            }
            for (int h0 = 0; h0 < Hd; h0 += PF) {
                float cg[PF], cu[PF];
#pragma unroll
                for (int j = 0; j < PF; j++) { cg[j] = bg[j]; cu[j] = bu[j]; }
                const int hn = h0 + PF;
                if (hn < Hd) {
#pragma unroll
                    for (int j = 0; j < PF; j++) {
                        bg[j] = wg[(hn + j) * Id];
                        bu[j] = wu[(hn + j) * Id];
                    }
                }
#pragma unroll
                for (int j = 0; j < PF; j++) {
                    u64 g2 = dup2(cg[j]);
                    u64 u2 = dup2(cu[j]);
                    const u64* xr = xsu + (h0 + j) * XPU;
#pragma unroll
                    for (int p = 0; p < NP; p++) {
                        u64 xv = xr[p];
                        a1[p] = ffma2(xv, g2, a1[p]);
                        a3[p] = ffma2(xv, u2, a3[p]);
                    }
                }
            }
            // activation: A = w_t * silu(h1) * h3  (padded slots have w=0)
#pragma unroll
            for (int p = 0; p < NP; p++) {
                float2 h1 = unpack2(a1[p]);
                float2 h3 = unpack2(a3[p]);
                float ax = s_w[2 * p]     * (h1.x / (1.0f + expf(-h1.x))) * h3.x;
                float ay = s_w[2 * p + 1] * (h1.y / (1.0f + expf(-h1.y))) * h3.y;
                as[i * XPF + 2 * p]     = ax;
                as[i * XPF + 2 * p + 1] = ay;
            }
        }
        __syncthreads();

        // ---- down projection: 4 column chunks of 256 ----
        for (int c = 0; c < Hd / Id; c++) {
            const int col = c * Id + tid;
            u64 acc[NP];
#pragma unroll
            for (int p = 0; p < NP; p++) acc[p] = 0ull;
            const float* wd = Wd + col;

            float bd[DPF];
#pragma unroll
            for (int j = 0; j < DPF; j++) bd[j] = wd[j * Hd];
            for (int i0 = 0; i0 < Id; i0 += DPF) {
                float cd[DPF];
#pragma unroll
                for (int j = 0; j < DPF; j++) cd[j] = bd[j];
                const int in = i0 + DPF;
                if (in < Id) {
#pragma unroll
                    for (int j = 0; j < DPF; j++) bd[j] = wd[(in + j) * Hd];
                }
#pragma unroll
                for (int j = 0; j < DPF; j++) {
                    u64 d2 = dup2(cd[j]);
                    const u64* ar = asu + (i0 + j) * XPU;
#pragma unroll
                    for (int p = 0; p < NP; p++) acc[p] = ffma2(ar[p], d2, acc[p]);
                }
            }
#pragma unroll
            for (int p = 0; p < NP; p++) {
                float2 v = unpack2(acc[p]);
                if (s_w[2 * p] != 0.0f)
                    atomicAdd(&y[(size_t)s_tok[2 * p] * Hd + col], v.x);
                if (s_w[2 * p + 1] != 0.0f)
                    atomicAdd(&y[(size_t)s_tok[2 * p + 1] * Hd + col], v.y);
            }
        }
        __syncthreads();   // before next chunk overwrites xs/as
    }
}

// ---------------- launch ----------------
extern "C" void kernel_launch(void* const* d_in, const int* in_sizes, int n_in,
                              void* d_out, int out_size) {
    const float* x       = (const float*)d_in[0];   // [1,1,T,H]
    const float* gate_w  = (const float*)d_in[1];   // [E,H]
    const float* e_bias  = (const float*)d_in[2];   // [E]
    const float* w_gate  = (const float*)d_in[3];   // [E,H,I]
    const float* w_up    = (const float*)d_in[4];   // [E,H,I]
    const float* w_down  = (const float*)d_in[5];   // [E,I,H]
    const float* sw_gate = (const float*)d_in[6];   // [H,I]
    const float* sw_up   = (const float*)d_in[7];   // [H,I]
    const float* sw_down = (const float*)d_in[8];   // [I,H]
    float* y = (float*)d_out;                       // [T*H] fp32

    const int SMEM_EXPERT = (Hd * XPF + Id * XPF) * (int)sizeof(float);  // 92160 B
    cudaFuncSetAttribute(expert_kernel,
                         cudaFuncAttributeMaxDynamicSharedMemorySize, SMEM_EXPERT);

    zero_kernel<<<(T * Hd + 255) / 256, 256>>>(y);
    gate_gemm<<<dim3(T / 64, E / 64), 256>>>(x, gate_w);
    route_kernel<<<(T + 31) / 32, 32>>>(e_bias);
    expert_kernel<<<E + T / TC, 256, SMEM_EXPERT>>>(
        x, w_gate, w_up, w_down, sw_gate, sw_up, sw_down, y);
}

// round 16
// speedup vs baseline: 1.6678x; 1.0039x over previous
#include <cuda_runtime.h>

// ---------------- problem constants ----------------
#define T      256
#define Hd     1024
#define E      256
#define Id     256
#define TOPK   8
#define NGROUP 8
#define GSIZE  32          // E / NGROUP
#define TOPKG  4
#define SCALE  2.5f

#define TC     16          // tokens per chunk per expert CTA
#define NP     8           // token pairs (TC/2)
#define XPF    18          // floats per smem row (16 tokens + 2 pad)
#define XPU    9           // u64 per smem row
#define PF     8           // prefetch depth, gate/up weight loads (x2 arrays = 16 LDG in flight)
#define DPF    16          // prefetch depth, down weight loads

typedef unsigned long long u64;

// ---------------- device scratch (no allocations allowed) ----------------
__device__ float g_logits[T * E];
__device__ int   g_cnt[E];
__device__ int   g_tok[E * T];
__device__ float g_wt[E * T];

// ---------------- packed f32x2 helpers ----------------
__device__ __forceinline__ u64 ffma2(u64 a, u64 b, u64 c) {
    u64 d;
    asm("fma.rn.f32x2 %0, %1, %2, %3;" : "=l"(d) : "l"(a), "l"(b), "l"(c));
    return d;
}
__device__ __forceinline__ u64 dup2(float v) {
    u64 d;
    asm("mov.b64 %0, {%1, %1};" : "=l"(d) : "f"(v));
    return d;
}
__device__ __forceinline__ float2 unpack2(u64 v) {
    float2 f;
    asm("mov.b64 {%0, %1}, %2;" : "=f"(f.x), "=f"(f.y) : "l"(v));
    return f;
}

// ---------------- kernel 0: zero output + expert counters ----------------
__global__ void zero_kernel(float* __restrict__ y) {
    int i = blockIdx.x * 256 + threadIdx.x;
    if (i < T * Hd) y[i] = 0.0f;
    if (i < E) g_cnt[i] = 0;
}

// ---------------- kernel 1: gate logits ----------------
__global__ __launch_bounds__(256) void gate_gemm(const float* __restrict__ X,
                                                 const float* __restrict__ W) {
    __shared__ float Xs[32][65];
    __shared__ float Ws[32][65];
    int t0 = blockIdx.x * 64;
    int e0 = blockIdx.y * 64;
    int tid = threadIdx.x;
    int tx = tid & 15;
    int ty = tid >> 4;
    float acc[4][4];
#pragma unroll
    for (int i = 0; i < 4; i++)
#pragma unroll
        for (int j = 0; j < 4; j++) acc[i][j] = 0.0f;

    for (int k0 = 0; k0 < Hd; k0 += 32) {
#pragma unroll
        for (int l = 0; l < 8; l++) {
            int idx = tid + l * 256;
            int r = idx >> 5;
            int kk = idx & 31;
            Xs[kk][r] = X[(size_t)(t0 + r) * Hd + k0 + kk];
            Ws[kk][r] = W[(size_t)(e0 + r) * Hd + k0 + kk];
        }
        __syncthreads();
#pragma unroll
        for (int kk = 0; kk < 32; kk++) {
            float a[4], b[4];
#pragma unroll
            for (int i = 0; i < 4; i++) a[i] = Xs[kk][ty * 4 + i];
#pragma unroll
            for (int j = 0; j < 4; j++) b[j] = Ws[kk][tx * 4 + j];
#pragma unroll
            for (int i = 0; i < 4; i++)
#pragma unroll
                for (int j = 0; j < 4; j++) acc[i][j] = fmaf(a[i], b[j], acc[i][j]);
        }
        __syncthreads();
    }
#pragma unroll
    for (int i = 0; i < 4; i++)
#pragma unroll
        for (int j = 0; j < 4; j++)
            g_logits[(t0 + ty * 4 + i) * E + e0 + tx * 4 + j] = acc[i][j];
}

// ---------------- kernel 2: per-token routing (noaux_tc) ----------------
__global__ void route_kernel(const float* __restrict__ e_bias) {
    int t = blockIdx.x * blockDim.x + threadIdx.x;
    if (t >= T) return;
    const float* lrow = g_logits + t * E;

    float sc[E];
#pragma unroll 4
    for (int e = 0; e < E; e++) {
        float s = 1.0f / (1.0f + expf(-lrow[e]));
        sc[e] = s + e_bias[e];
    }

    float gs[NGROUP];
    for (int g = 0; g < NGROUP; g++) {
        float m1 = -1e30f, m2 = -1e30f;
        for (int j = 0; j < GSIZE; j++) {
            float v = sc[g * GSIZE + j];
            if (v > m1) { m2 = m1; m1 = v; }
            else if (v > m2) { m2 = v; }
        }
        gs[g] = m1 + m2;
    }

    unsigned gmask = 0;
    for (int r = 0; r < TOPKG; r++) {
        float best = -1e30f; int bi = 0;
        for (int g = 0; g < NGROUP; g++)
            if (!((gmask >> g) & 1u) && gs[g] > best) { best = gs[g]; bi = g; }
        gmask |= 1u << bi;
    }

    float bv[TOPK]; int bix[TOPK];
#pragma unroll
    for (int r = 0; r < TOPK; r++) { bv[r] = -1e30f; bix[r] = 0; }
    for (int e = 0; e < E; e++) {
        if (!((gmask >> (e >> 5)) & 1u)) continue;
        float v = sc[e];
        if (v <= bv[TOPK - 1]) continue;
        int pos = TOPK - 1;
        while (pos > 0 && bv[pos - 1] < v) {
            bv[pos] = bv[pos - 1]; bix[pos] = bix[pos - 1]; pos--;
        }
        bv[pos] = v; bix[pos] = e;
    }

    float wv[TOPK]; float wsum = 0.0f;
#pragma unroll
    for (int r = 0; r < TOPK; r++) {
        wv[r] = 1.0f / (1.0f + expf(-lrow[bix[r]]));
        wsum += wv[r];
    }
    float inv = SCALE / (wsum + 1e-20f);
#pragma unroll
    for (int r = 0; r < TOPK; r++) {
        int e = bix[r];
        int pos = atomicAdd(&g_cnt[e], 1);
        g_tok[e * T + pos] = t;
        g_wt[e * T + pos]  = wv[r] * inv;
    }
}

// ---------------- kernel 3: expert MLPs (routed + shared) ----------------
// Register double-buffered weight prefetch: keeps 16 LDGs in flight per warp
// (gate/up) so per-SM outstanding bytes (~32KB) exceed the BW*latency product
// needed to saturate DRAM.
__global__ __launch_bounds__(256, 2) void expert_kernel(
    const float* __restrict__ x,
    const float* __restrict__ w_gate, const float* __restrict__ w_up,
    const float* __restrict__ w_down,
    const float* __restrict__ sw_gate, const float* __restrict__ sw_up,
    const float* __restrict__ sw_down,
    float* __restrict__ y)
{
    extern __shared__ float smem[];
    float* xs = smem;                      // Hd * XPF floats
    float* as = smem + Hd * XPF;           // Id * XPF floats
    const u64* xsu = (const u64*)xs;
    const u64* asu = (const u64*)as;
    __shared__ int   s_tok[TC];
    __shared__ float s_w[TC];

    const int tid = threadIdx.x;
    const int e = blockIdx.x;
    const bool sh = (e >= E);

    const float *Wg, *Wu, *Wd;
    int nt, base = 0;
    if (sh) {
        Wg = sw_gate; Wu = sw_up; Wd = sw_down;
        nt = TC; base = (e - E) * TC;
    } else {
        size_t off = (size_t)e * Hd * Id;
        Wg = w_gate + off; Wu = w_up + off; Wd = w_down + off;
        nt = g_cnt[e];
    }
    const int nchunk = (nt + TC - 1) / TC;

    for (int ch = 0; ch < nchunk; ch++) {
        if (tid < TC) {
            int slot = ch * TC + tid;
            if (sh)             { s_tok[tid] = base + tid;          s_w[tid] = 1.0f; }
            else if (slot < nt) { s_tok[tid] = g_tok[e * T + slot]; s_w[tid] = g_wt[e * T + slot]; }
            else                { s_tok[tid] = 0;                   s_w[tid] = 0.0f; }
        }
        __syncthreads();

        // gather X rows (coalesced LDG)
        for (int idx = tid; idx < TC * Hd; idx += 256) {
            int t = idx >> 10;          // / Hd
            int h = idx & (Hd - 1);
            xs[h * XPF + t] = x[(size_t)s_tok[t] * Hd + h];
        }
        __syncthreads();

        // ---- gate + up projections: thread owns column i of I ----
        {
            const int i = tid;
            u64 a1[NP], a3[NP];
#pragma unroll
            for (int p = 0; p < NP; p++) { a1[p] = 0ull; a3[p] = 0ull; }
            const float* wg = Wg + i;
            const float* wu = Wu + i;

            float bg[PF], bu[PF];
#pragma unroll
            for (int j = 0; j < PF; j++) {
                bg[j] = wg[j * Id];
                bu[j] = wu[j * Id];
            }
            for (int h0 = 0; h0 < Hd; h0 += PF) {
                float cg[PF], cu[PF];
#pragma unroll
                for (int j = 0; j < PF; j++) { cg[j] = bg[j]; cu[j] = bu[j]; }
                const int hn = h0 + PF;
                if (hn < Hd) {
#pragma unroll
                    for (int j = 0; j < PF; j++) {
                        bg[j] = wg[(hn + j) * Id];
                        bu[j] = wu[(hn + j) * Id];
                    }
                }
#pragma unroll
                for (int j = 0; j < PF; j++) {
                    u64 g2 = dup2(cg[j]);
                    u64 u2 = dup2(cu[j]);
                    const u64* xr = xsu + (h0 + j) * XPU;
#pragma unroll
                    for (int p = 0; p < NP; p++) {
                        u64 xv = xr[p];
                        a1[p] = ffma2(xv, g2, a1[p]);
                        a3[p] = ffma2(xv, u2, a3[p]);
                    }
                }
            }
            // activation: A = w_t * silu(h1) * h3  (padded slots have w=0)
#pragma unroll
            for (int p = 0; p < NP; p++) {
                float2 h1 = unpack2(a1[p]);
                float2 h3 = unpack2(a3[p]);
                float ax = s_w[2 * p]     * (h1.x / (1.0f + expf(-h1.x))) * h3.x;
                float ay = s_w[2 * p + 1] * (h1.y / (1.0f + expf(-h1.y))) * h3.y;
                as[i * XPF + 2 * p]     = ax;
                as[i * XPF + 2 * p + 1] = ay;
            }
        }
        __syncthreads();

        // ---- down projection: 4 column chunks of 256 ----
        for (int c = 0; c < Hd / Id; c++) {
            const int col = c * Id + tid;
            u64 acc[NP];
#pragma unroll
            for (int p = 0; p < NP; p++) acc[p] = 0ull;
            const float* wd = Wd + col;

            float bd[DPF];
#pragma unroll
            for (int j = 0; j < DPF; j++) bd[j] = wd[j * Hd];
            for (int i0 = 0; i0 < Id; i0 += DPF) {
                float cd[DPF];
#pragma unroll
                for (int j = 0; j < DPF; j++) cd[j] = bd[j];
                const int in = i0 + DPF;
                if (in < Id) {
#pragma unroll
                    for (int j = 0; j < DPF; j++) bd[j] = wd[(in + j) * Hd];
                }
#pragma unroll
                for (int j = 0; j < DPF; j++) {
                    u64 d2 = dup2(cd[j]);
                    const u64* ar = asu + (i0 + j) * XPU;
#pragma unroll
                    for (int p = 0; p < NP; p++) acc[p] = ffma2(ar[p], d2, acc[p]);
                }
            }
#pragma unroll
            for (int p = 0; p < NP; p++) {
                float2 v = unpack2(acc[p]);
                if (s_w[2 * p] != 0.0f)
                    atomicAdd(&y[(size_t)s_tok[2 * p] * Hd + col], v.x);
                if (s_w[2 * p + 1] != 0.0f)
                    atomicAdd(&y[(size_t)s_tok[2 * p + 1] * Hd + col], v.y);
            }
        }
        __syncthreads();   // before next chunk overwrites xs/as
    }
}

// ---------------- launch ----------------
extern "C" void kernel_launch(void* const* d_in, const int* in_sizes, int n_in,
                              void* d_out, int out_size) {
    const float* x       = (const float*)d_in[0];   // [1,1,T,H]
    const float* gate_w  = (const float*)d_in[1];   // [E,H]
    const float* e_bias  = (const float*)d_in[2];   // [E]
    const float* w_gate  = (const float*)d_in[3];   // [E,H,I]
    const float* w_up    = (const float*)d_in[4];   // [E,H,I]
    const float* w_down  = (const float*)d_in[5];   // [E,I,H]
    const float* sw_gate = (const float*)d_in[6];   // [H,I]
    const float* sw_up   = (const float*)d_in[7];   // [H,I]
    const float* sw_down = (const float*)d_in[8];   // [I,H]
    float* y = (float*)d_out;                       // [T*H] fp32

    const int SMEM_EXPERT = (Hd * XPF + Id * XPF) * (int)sizeof(float);  // 92160 B
    cudaFuncSetAttribute(expert_kernel,
                         cudaFuncAttributeMaxDynamicSharedMemorySize, SMEM_EXPERT);

    zero_kernel<<<(T * Hd + 255) / 256, 256>>>(y);
    gate_gemm<<<dim3(T / 64, E / 64), 256>>>(x, gate_w);
    route_kernel<<<(T + 31) / 32, 32>>>(e_bias);
    expert_kernel<<<E + T / TC, 256, SMEM_EXPERT>>>(
        x, w_gate, w_up, w_down, sw_gate, sw_up, sw_down, y);
}